// round 15
// baseline (speedup 1.0000x reference)
#include <cuda_runtime.h>

#define SLOPE 0.3f
#define ATTN_SCALE 0.17677669529663687f   // 32^-0.5
#define LN_EPS 1e-3f

// ---- scratch (no allocs allowed) -------------------------------------------
__device__ float g_bias[4096];        // bias_table[rel_idx]  (64x64)
// hidden scratch, layout [chunk16][token(2*512*512)][8ch]  (256MB each)
__device__ float g_h[67108864];
__device__ float g_h2[67108864];

// ---- packed f32x2 helpers ----------------------------------------------------
__device__ __forceinline__ unsigned long long pk2(float a, float b) {
    unsigned long long r;
    asm("mov.b64 %0, {%1, %2};" : "=l"(r)
        : "r"(__float_as_uint(a)), "r"(__float_as_uint(b)));
    return r;
}
__device__ __forceinline__ void upk2(unsigned long long v, float& a, float& b) {
    unsigned int x, y;
    asm("mov.b64 {%0, %1}, %2;" : "=r"(x), "=r"(y) : "l"(v));
    a = __uint_as_float(x); b = __uint_as_float(y);
}
__device__ __forceinline__ void fma2(unsigned long long& d,
                                     unsigned long long a, unsigned long long b) {
    asm("fma.rn.f32x2 %0, %1, %2, %0;" : "+l"(d) : "l"(a), "l"(b));
}
// gelu via A&S 7.1.26 erf approximation, |abs err| < 1.5e-7 (effectively exact
// at our 1e-3 tolerance), ~12 ops instead of libdevice erff's long polynomial.
__device__ __forceinline__ float gelu_f(float z) {
    float x = fabsf(z) * 0.70710678118654752f;
    float t = __fdividef(1.0f, fmaf(0.3275911f, x, 1.0f));
    float p = t * fmaf(t, fmaf(t, fmaf(t, fmaf(t, 1.061405429f, -1.453152027f),
                                       1.421413741f), -0.284496736f), 0.254829592f);
    float e = __expf(-x * x);
    float er = copysignf(fmaf(-p, e, 1.0f), z);
    return 0.5f * z * (1.0f + er);
}
__device__ __forceinline__ float leaky_f(float z) {
    return z >= 0.f ? z : SLOPE * z;
}

// ---- K0: gather relative-position bias --------------------------------------
__global__ void kbias(const float* __restrict__ table, const int* __restrict__ idx) {
    int i = blockIdx.x * 256 + threadIdx.x;
    if (i < 4096) g_bias[i] = table[idx[i]];
}

// ---- KA: fused LN1 + window attention + proj + residual  ->  x2 (= d_out) ---
// 1 block = 2 windows (128 threads), 1 thread = 1 token.
__global__ __launch_bounds__(128) void ka_attn(
    const float* __restrict__ x,
    const float* __restrict__ g1, const float* __restrict__ be1,
    const float* __restrict__ Wq, const float* __restrict__ bq,
    const float* __restrict__ Wkv, const float* __restrict__ bkv,
    const float* __restrict__ Wp, const float* __restrict__ bp,
    float* __restrict__ out)
{
    __shared__ __align__(16) float sWq[1024];
    __shared__ __align__(16) float sWkv[2048];
    __shared__ __align__(16) float sWp[1024];
    __shared__ __align__(16) float ks[2][2048];   // k transposed [c][m], per window
    __shared__ __align__(16) float vs[2][2048];   // v transposed [c][m], per window
    __shared__ float sbq[32], sbp[32], sg1[32], sbe1[32], sbkv[64];

    const int t = threadIdx.x;
    {   // vectorized weight staging
        const float4* Wq4  = reinterpret_cast<const float4*>(Wq);
        const float4* Wp4  = reinterpret_cast<const float4*>(Wp);
        const float4* Wkv4 = reinterpret_cast<const float4*>(Wkv);
        float4* sq4 = reinterpret_cast<float4*>(sWq);
        float4* sp4 = reinterpret_cast<float4*>(sWp);
        float4* sk4 = reinterpret_cast<float4*>(sWkv);
        for (int i = t; i < 256; i += 128) { sq4[i] = Wq4[i]; sp4[i] = Wp4[i]; }
        for (int i = t; i < 512; i += 128) sk4[i] = Wkv4[i];
        if (t < 32) { sbq[t] = bq[t]; sbp[t] = bp[t]; sg1[t] = g1[t]; sbe1[t] = be1[t]; }
        if (t < 64) sbkv[t] = bkv[t];
    }

    const int wloc = t >> 6;                      // which of the 2 windows
    const int tw   = t & 63;                      // token within window
    const int w  = blockIdx.x * 2 + wloc;
    const int b  = w >> 12;
    const int wy = (w >> 6) & 63;
    const int wx = w & 63;
    const int py = wy * 8 + (tw >> 3);
    const int px = wx * 8 + (tw & 7);
    const int base = (b * 262144 + py * 512 + px) * 32;

    // ---- LN1 ----
    float xn[32];
    {
        const float4* xp = reinterpret_cast<const float4*>(x + base);
        #pragma unroll
        for (int i = 0; i < 8; i++) {
            float4 v4 = xp[i];
            xn[4*i+0] = v4.x; xn[4*i+1] = v4.y; xn[4*i+2] = v4.z; xn[4*i+3] = v4.w;
        }
        float mu = 0.f;
        #pragma unroll
        for (int c = 0; c < 32; c++) mu += xn[c];
        mu *= 0.03125f;
        float var = 0.f;
        #pragma unroll
        for (int c = 0; c < 32; c++) { float d = xn[c] - mu; var += d * d; }
        float rs = rsqrtf(var * 0.03125f + LN_EPS);
        __syncthreads();   // weights staged
        #pragma unroll
        for (int c = 0; c < 32; c++) xn[c] = (xn[c] - mu) * rs * sg1[c] + sbe1[c];
    }

    // ---- q = leaky(xn @ Wq + bq) * SCALE ----
    float q[32];
    {
        unsigned long long acc[16];
        #pragma unroll
        for (int i = 0; i < 16; i++) acc[i] = 0ull;
        #pragma unroll 4
        for (int k = 0; k < 32; k++) {
            unsigned long long xk2 = pk2(xn[k], xn[k]);
            const ulonglong2* wr = reinterpret_cast<const ulonglong2*>(&sWq[k * 32]);
            #pragma unroll
            for (int j = 0; j < 8; j++) {
                ulonglong2 u = wr[j];
                fma2(acc[2*j+0], xk2, u.x);
                fma2(acc[2*j+1], xk2, u.y);
            }
        }
        #pragma unroll
        for (int i = 0; i < 16; i++) {
            float a0, a1; upk2(acc[i], a0, a1);
            q[2*i+0] = leaky_f(a0 + sbq[2*i+0]) * ATTN_SCALE;
            q[2*i+1] = leaky_f(a1 + sbq[2*i+1]) * ATTN_SCALE;
        }
    }

    // ---- k, v = leaky(xn @ Wkv + bkv), stored transposed [c][m] ----
    #pragma unroll
    for (int hh = 0; hh < 2; hh++) {
        unsigned long long acc[16];
        #pragma unroll
        for (int i = 0; i < 16; i++) acc[i] = 0ull;
        #pragma unroll 4
        for (int k = 0; k < 32; k++) {
            unsigned long long xk2 = pk2(xn[k], xn[k]);
            const ulonglong2* wr =
                reinterpret_cast<const ulonglong2*>(&sWkv[k * 64 + hh * 32]);
            #pragma unroll
            for (int j = 0; j < 8; j++) {
                ulonglong2 u = wr[j];
                fma2(acc[2*j+0], xk2, u.x);
                fma2(acc[2*j+1], xk2, u.y);
            }
        }
        float* dst = hh ? vs[wloc] : ks[wloc];
        #pragma unroll
        for (int i = 0; i < 16; i++) {
            float a0, a1; upk2(acc[i], a0, a1);
            dst[(2*i+0) * 64 + tw] = leaky_f(a0 + sbkv[hh * 32 + 2*i+0]);
            dst[(2*i+1) * 64 + tw] = leaky_f(a1 + sbkv[hh * 32 + 2*i+1]);
        }
    }
    __syncthreads();

    // ---- scores: a[m] = q . k[:,m] + bias[tw,m] ----
    float a[64];
    {
        unsigned long long aa[32];
        #pragma unroll
        for (int i = 0; i < 32; i++) aa[i] = 0ull;
        #pragma unroll 2
        for (int c = 0; c < 32; c++) {
            unsigned long long q2 = pk2(q[c], q[c]);
            const ulonglong2* kr =
                reinterpret_cast<const ulonglong2*>(&ks[wloc][c * 64]);
            #pragma unroll
            for (int j = 0; j < 16; j++) {
                ulonglong2 u = kr[j];
                fma2(aa[2*j+0], q2, u.x);
                fma2(aa[2*j+1], q2, u.y);
            }
        }
        const float* brow = &g_bias[tw * 64];
        #pragma unroll
        for (int i = 0; i < 32; i++) {
            float a0, a1; upk2(aa[i], a0, a1);
            a[2*i+0] = a0 + brow[2*i+0];
            a[2*i+1] = a1 + brow[2*i+1];
        }
    }

    // ---- softmax ----
    float mx = a[0];
    #pragma unroll
    for (int m = 1; m < 64; m++) mx = fmaxf(mx, a[m]);
    float sum = 0.f;
    #pragma unroll
    for (int m = 0; m < 64; m++) { a[m] = __expf(a[m] - mx); sum += a[m]; }
    float inv = 1.f / sum;
    unsigned long long ap[32];
    #pragma unroll
    for (int i = 0; i < 32; i++) ap[i] = pk2(a[2*i+0] * inv, a[2*i+1] * inv);

    // ---- out = attn @ v ----
    float o[32];
    #pragma unroll 2
    for (int c = 0; c < 32; c++) {
        unsigned long long acc0 = 0ull, acc1 = 0ull;
        const ulonglong2* vr = reinterpret_cast<const ulonglong2*>(&vs[wloc][c * 64]);
        #pragma unroll
        for (int j = 0; j < 16; j++) {
            ulonglong2 u = vr[j];
            fma2(acc0, ap[2*j+0], u.x);
            fma2(acc1, ap[2*j+1], u.y);
        }
        float l0, h0, l1, h1;
        upk2(acc0, l0, h0); upk2(acc1, l1, h1);
        o[c] = (l0 + h0) + (l1 + h1);
    }

    // ---- proj + residual ----
    unsigned long long pa[16];
    #pragma unroll
    for (int i = 0; i < 16; i++) pa[i] = 0ull;
    #pragma unroll 4
    for (int c = 0; c < 32; c++) {
        unsigned long long o2 = pk2(o[c], o[c]);
        const ulonglong2* wr = reinterpret_cast<const ulonglong2*>(&sWp[c * 32]);
        #pragma unroll
        for (int j = 0; j < 8; j++) {
            ulonglong2 u = wr[j];
            fma2(pa[2*j+0], o2, u.x);
            fma2(pa[2*j+1], o2, u.y);
        }
    }
    const float4* xp2 = reinterpret_cast<const float4*>(x + base);
    float4* op = reinterpret_cast<float4*>(out + base);
    #pragma unroll
    for (int i = 0; i < 8; i++) {
        float4 xv = xp2[i];
        float a0, a1, b0, b1;
        upk2(pa[2*i+0], a0, a1);
        upk2(pa[2*i+1], b0, b1);
        float4 r;
        r.x = xv.x + a0 + sbp[4*i+0];
        r.y = xv.y + a1 + sbp[4*i+1];
        r.z = xv.z + b0 + sbp[4*i+2];
        r.w = xv.w + b1 + sbp[4*i+3];
        op[i] = r;
    }
}

// ---- KB1: LN2 + W1 + gelu  ->  g_h [chunk][token][8] --------------------------
__global__ __launch_bounds__(256) void kb1(
    const float* __restrict__ x2,
    const float* __restrict__ g2, const float* __restrict__ be2,
    const float* __restrict__ W1, const float* __restrict__ b1m)
{
    __shared__ __align__(16) float sW1[4096];
    __shared__ float sb1[128], sg[32], sb[32];
    const int t = threadIdx.x;
    {
        const float4* W14 = reinterpret_cast<const float4*>(W1);
        float4* s4 = reinterpret_cast<float4*>(sW1);
        for (int i = t; i < 1024; i += 256) s4[i] = W14[i];
    }
    if (t < 128) sb1[t] = b1m[t];
    if (t < 32) { sg[t] = g2[t]; sb[t] = be2[t]; }

    const int tok = blockIdx.x * 256 + t;
    float y[32];
    const float4* xp = reinterpret_cast<const float4*>(x2 + tok * 32);
    #pragma unroll
    for (int i = 0; i < 8; i++) {
        float4 v4 = xp[i];
        y[4*i+0] = v4.x; y[4*i+1] = v4.y; y[4*i+2] = v4.z; y[4*i+3] = v4.w;
    }
    float mu = 0.f;
    #pragma unroll
    for (int c = 0; c < 32; c++) mu += y[c];
    mu *= 0.03125f;
    float var = 0.f;
    #pragma unroll
    for (int c = 0; c < 32; c++) { float d = y[c] - mu; var += d * d; }
    float rs = rsqrtf(var * 0.03125f + LN_EPS);
    __syncthreads();
    #pragma unroll
    for (int c = 0; c < 32; c++) y[c] = (y[c] - mu) * rs * sg[c] + sb[c];

    #pragma unroll
    for (int p = 0; p < 4; p++) {
        unsigned long long acc[16];
        #pragma unroll
        for (int i = 0; i < 16; i++) acc[i] = 0ull;
        #pragma unroll 4
        for (int c = 0; c < 32; c++) {
            unsigned long long y2 = pk2(y[c], y[c]);
            const ulonglong2* wr =
                reinterpret_cast<const ulonglong2*>(&sW1[c * 128 + p * 32]);
            #pragma unroll
            for (int j = 0; j < 8; j++) {
                ulonglong2 u = wr[j];
                fma2(acc[2*j+0], y2, u.x);
                fma2(acc[2*j+1], y2, u.y);
            }
        }
        #pragma unroll
        for (int i = 0; i < 8; i++) {
            float v0, v1, v2, v3;
            upk2(acc[2*i+0], v0, v1);
            upk2(acc[2*i+1], v2, v3);
            int jb = p * 32 + 4 * i;
            float4 r;
            r.x = gelu_f(v0 + sb1[jb+0]);
            r.y = gelu_f(v1 + sb1[jb+1]);
            r.z = gelu_f(v2 + sb1[jb+2]);
            r.w = gelu_f(v3 + sb1[jb+3]);
            // g_h layout [chunk16][token][8]
            __stcs(reinterpret_cast<float4*>(
                &g_h[((size_t)(jb >> 3) * 524288 + tok) * 8 + (jb & 7)]), r);
        }
    }
}

// ---- KCONV: depthwise 3x3 + gelu for ONE 8-ch chunk per block  -> g_h2 --------
// Grid: [2 batch][16 chunk][32 ty][16 tx]; block 256 thr; tile 32x16 px;
// each thread: 2 vertically-adjacent pixels x 8 channels.
__global__ __launch_bounds__(256) void kconv(
    const float* __restrict__ dwk, const float* __restrict__ dwb)
{
    __shared__ float sp[8 * 648];     // 8 planes of 18 x 36 (stride 36)
    __shared__ float sk[72], skb[8];

    const int t  = threadIdx.x;
    const int bb = blockIdx.x;
    const int b     = bb >> 13;
    const int chunk = (bb >> 9) & 15;
    const int ty0   = ((bb >> 4) & 31) * 16;
    const int tx0   = (bb & 15) * 32;
    const int plane = b * 262144;

    if (t < 72) sk[t] = dwk[(t >> 3) * 128 + chunk * 8 + (t & 7)];
    if (t < 8)  skb[t] = dwb[chunk * 8 + t];

    // halo 18 x 34, 8 channels (32B per position = 2 float4)
    const size_t cbase = (size_t)chunk * 524288 + plane;
    for (int i = t; i < 1224; i += 256) {
        int pos = i >> 1, half = i & 1;
        int pr = pos / 34, pc = pos - pr * 34;
        int gy = ty0 - 1 + pr, gx = tx0 - 1 + pc;
        float4 v = make_float4(0.f, 0.f, 0.f, 0.f);
        if ((unsigned)gy < 512u && (unsigned)gx < 512u)
            v = *reinterpret_cast<const float4*>(
                &g_h[(cbase + gy * 512 + gx) * 8 + half * 4]);
        float* d = &sp[(half * 4) * 648 + pr * 36 + pc];
        d[0]        = v.x;
        d[648]      = v.y;
        d[2 * 648]  = v.z;
        d[3 * 648]  = v.w;
    }
    __syncthreads();

    const int cx  = t & 31;
    const int ry2 = (t >> 5) * 2;            // rows ry2, ry2+1 of the tile
    float o0[8], o1[8];
    #pragma unroll
    for (int c = 0; c < 8; c++) {
        const float* pl = &sp[c * 648 + ry2 * 36 + cx];
        float r0[3], r1[3], r2[3], r3[3];
        #pragma unroll
        for (int d = 0; d < 3; d++) {
            r0[d] = pl[d];
            r1[d] = pl[36 + d];
            r2[d] = pl[72 + d];
            r3[d] = pl[108 + d];
        }
        float s0 = 0.f, s1 = 0.f;
        #pragma unroll
        for (int kx = 0; kx < 3; kx++) {
            float k0 = sk[(0 + kx) * 8 + c];
            float k1 = sk[(3 + kx) * 8 + c];
            float k2 = sk[(6 + kx) * 8 + c];
            s0 += r0[kx] * k0 + r1[kx] * k1 + r2[kx] * k2;
            s1 += r1[kx] * k0 + r2[kx] * k1 + r3[kx] * k2;
        }
        o0[c] = gelu_f(s0 + skb[c]);
        o1[c] = gelu_f(s1 + skb[c]);
    }

    const size_t tok0 = cbase + (size_t)(ty0 + ry2) * 512 + tx0 + cx;
    float4* w0 = reinterpret_cast<float4*>(&g_h2[tok0 * 8]);
    float4* w1 = reinterpret_cast<float4*>(&g_h2[(tok0 + 512) * 8]);
    w0[0] = make_float4(o0[0], o0[1], o0[2], o0[3]);
    w0[1] = make_float4(o0[4], o0[5], o0[6], o0[7]);
    w1[0] = make_float4(o1[0], o1[1], o1[2], o1[3]);
    w1[1] = make_float4(o1[4], o1[5], o1[6], o1[7]);
}

// ---- KW2: out += gelu_conv_hidden @ W2 + b2  (token-parallel) ------------------
__global__ __launch_bounds__(256) void kw2(
    const float* __restrict__ W2, const float* __restrict__ b2m,
    float* __restrict__ out)
{
    __shared__ __align__(16) float sW2[4096];
    __shared__ float sb2[32];
    const int t = threadIdx.x;
    {
        const float4* W24 = reinterpret_cast<const float4*>(W2);
        float4* s4 = reinterpret_cast<float4*>(sW2);
        for (int i = t; i < 1024; i += 256) s4[i] = W24[i];
    }
    if (t < 32) sb2[t] = b2m[t];
    __syncthreads();

    const int tok = blockIdx.x * 256 + t;

    unsigned long long acc[16];
    #pragma unroll
    for (int i = 0; i < 16; i++) acc[i] = 0ull;

    #pragma unroll 2
    for (int chunk = 0; chunk < 16; chunk++) {
        const float4* hp = reinterpret_cast<const float4*>(
            &g_h2[((size_t)chunk * 524288 + tok) * 8]);
        float4 h0 = hp[0], h1 = hp[1];
        float hv[8] = {h0.x, h0.y, h0.z, h0.w, h1.x, h1.y, h1.z, h1.w};
        #pragma unroll
        for (int c = 0; c < 8; c++) {
            const int ch = chunk * 8 + c;
            unsigned long long s2 = pk2(hv[c], hv[c]);
            const ulonglong2* wr = reinterpret_cast<const ulonglong2*>(&sW2[ch * 32]);
            #pragma unroll
            for (int j = 0; j < 8; j++) {
                ulonglong2 u = wr[j];
                fma2(acc[2*j+0], s2, u.x);
                fma2(acc[2*j+1], s2, u.y);
            }
        }
    }

    const int base = tok * 32;
    #pragma unroll
    for (int i = 0; i < 8; i++) {
        float4 xv = *reinterpret_cast<const float4*>(out + base + 4 * i);
        float a0, a1, b0, b1;
        upk2(acc[2*i+0], a0, a1);
        upk2(acc[2*i+1], b0, b1);
        float4 r;
        r.x = xv.x + a0 + sb2[4*i+0];
        r.y = xv.y + a1 + sb2[4*i+1];
        r.z = xv.z + b0 + sb2[4*i+2];
        r.w = xv.w + b1 + sb2[4*i+3];
        *reinterpret_cast<float4*>(out + base + 4 * i) = r;
    }
}

// ---- launch -------------------------------------------------------------------
extern "C" void kernel_launch(void* const* d_in, const int* in_sizes, int n_in,
                              void* d_out, int out_size) {
    const float* x          = (const float*)d_in[0];
    const float* g1         = (const float*)d_in[1];
    const float* beta1      = (const float*)d_in[2];
    const float* Wq         = (const float*)d_in[3];
    const float* bq         = (const float*)d_in[4];
    const float* Wkv        = (const float*)d_in[5];
    const float* bkv        = (const float*)d_in[6];
    const float* bias_table = (const float*)d_in[7];
    const float* Wp         = (const float*)d_in[8];
    const float* bp         = (const float*)d_in[9];
    const float* g2         = (const float*)d_in[10];
    const float* beta2      = (const float*)d_in[11];
    const float* W1         = (const float*)d_in[12];
    const float* b1m        = (const float*)d_in[13];
    const float* dw_k       = (const float*)d_in[14];
    const float* dw_b       = (const float*)d_in[15];
    const float* W2         = (const float*)d_in[16];
    const float* b2m        = (const float*)d_in[17];
    const int*   rel_idx    = (const int*)d_in[18];
    float* out = (float*)d_out;

    kbias<<<16, 256>>>(bias_table, rel_idx);
    ka_attn<<<4096, 128>>>(x, g1, beta1, Wq, bq, Wkv, bkv, Wp, bp, out);
    kb1<<<2048, 256>>>(out, g2, beta2, W1, b1m);
    kconv<<<16384, 256>>>(dw_k, dw_b);
    kw2<<<2048, 256>>>(W2, b2m, out);
}

// round 16
// speedup vs baseline: 1.1756x; 1.1756x over previous
#include <cuda_runtime.h>
#include <cuda_fp16.h>

#define SLOPE 0.3f
#define ATTN_SCALE 0.17677669529663687f   // 32^-0.5
#define LN_EPS 1e-3f

// ---- scratch (no allocs allowed) -------------------------------------------
__device__ float g_bias[4096];        // bias_table[rel_idx]  (64x64)
// hidden scratch h (pre-conv), layout [chunk16][token(2*512*512)][8ch], fp32
__device__ float g_h[67108864];
// conv output h2, same layout, fp16 (halves kconv-write + kw2-read traffic)
__device__ __half g_h2[67108864];

// ---- packed f32x2 helpers ----------------------------------------------------
__device__ __forceinline__ unsigned long long pk2(float a, float b) {
    unsigned long long r;
    asm("mov.b64 %0, {%1, %2};" : "=l"(r)
        : "r"(__float_as_uint(a)), "r"(__float_as_uint(b)));
    return r;
}
__device__ __forceinline__ void upk2(unsigned long long v, float& a, float& b) {
    unsigned int x, y;
    asm("mov.b64 {%0, %1}, %2;" : "=r"(x), "=r"(y) : "l"(v));
    a = __uint_as_float(x); b = __uint_as_float(y);
}
__device__ __forceinline__ void fma2(unsigned long long& d,
                                     unsigned long long a, unsigned long long b) {
    asm("fma.rn.f32x2 %0, %1, %2, %0;" : "+l"(d) : "l"(a), "l"(b));
}
// exact gelu via libdevice erff — fewer live registers (measured best in kconv)
__device__ __forceinline__ float gelu_exact(float z) {
    return 0.5f * z * (1.0f + erff(z * 0.70710678118654752f));
}
// A&S 7.1.26 erf gelu, |abs err| < 1.5e-7 — fewer ALU ops (used in kb1)
__device__ __forceinline__ float gelu_fast(float z) {
    float x = fabsf(z) * 0.70710678118654752f;
    float t = __fdividef(1.0f, fmaf(0.3275911f, x, 1.0f));
    float p = t * fmaf(t, fmaf(t, fmaf(t, fmaf(t, 1.061405429f, -1.453152027f),
                                       1.421413741f), -0.284496736f), 0.254829592f);
    float e = __expf(-x * x);
    float er = copysignf(fmaf(-p, e, 1.0f), z);
    return 0.5f * z * (1.0f + er);
}
__device__ __forceinline__ float leaky_f(float z) {
    return z >= 0.f ? z : SLOPE * z;
}

// ---- K0: gather relative-position bias --------------------------------------
__global__ void kbias(const float* __restrict__ table, const int* __restrict__ idx) {
    int i = blockIdx.x * 256 + threadIdx.x;
    if (i < 4096) g_bias[i] = table[idx[i]];
}

// ---- KA: fused LN1 + window attention + proj + residual  ->  x2 (= d_out) ---
// 1 block = 2 windows (128 threads), 1 thread = 1 token.
__global__ __launch_bounds__(128) void ka_attn(
    const float* __restrict__ x,
    const float* __restrict__ g1, const float* __restrict__ be1,
    const float* __restrict__ Wq, const float* __restrict__ bq,
    const float* __restrict__ Wkv, const float* __restrict__ bkv,
    const float* __restrict__ Wp, const float* __restrict__ bp,
    float* __restrict__ out)
{
    __shared__ __align__(16) float sWq[1024];
    __shared__ __align__(16) float sWkv[2048];
    __shared__ __align__(16) float sWp[1024];
    __shared__ __align__(16) float ks[2][2048];   // k transposed [c][m], per window
    __shared__ __align__(16) float vs[2][2048];   // v transposed [c][m], per window
    __shared__ float sbq[32], sbp[32], sg1[32], sbe1[32], sbkv[64];

    const int t = threadIdx.x;
    {   // vectorized weight staging
        const float4* Wq4  = reinterpret_cast<const float4*>(Wq);
        const float4* Wp4  = reinterpret_cast<const float4*>(Wp);
        const float4* Wkv4 = reinterpret_cast<const float4*>(Wkv);
        float4* sq4 = reinterpret_cast<float4*>(sWq);
        float4* sp4 = reinterpret_cast<float4*>(sWp);
        float4* sk4 = reinterpret_cast<float4*>(sWkv);
        for (int i = t; i < 256; i += 128) { sq4[i] = Wq4[i]; sp4[i] = Wp4[i]; }
        for (int i = t; i < 512; i += 128) sk4[i] = Wkv4[i];
        if (t < 32) { sbq[t] = bq[t]; sbp[t] = bp[t]; sg1[t] = g1[t]; sbe1[t] = be1[t]; }
        if (t < 64) sbkv[t] = bkv[t];
    }

    const int wloc = t >> 6;                      // which of the 2 windows
    const int tw   = t & 63;                      // token within window
    const int w  = blockIdx.x * 2 + wloc;
    const int b  = w >> 12;
    const int wy = (w >> 6) & 63;
    const int wx = w & 63;
    const int py = wy * 8 + (tw >> 3);
    const int px = wx * 8 + (tw & 7);
    const int base = (b * 262144 + py * 512 + px) * 32;

    // ---- LN1 ----
    float xn[32];
    {
        const float4* xp = reinterpret_cast<const float4*>(x + base);
        #pragma unroll
        for (int i = 0; i < 8; i++) {
            float4 v4 = xp[i];
            xn[4*i+0] = v4.x; xn[4*i+1] = v4.y; xn[4*i+2] = v4.z; xn[4*i+3] = v4.w;
        }
        float mu = 0.f;
        #pragma unroll
        for (int c = 0; c < 32; c++) mu += xn[c];
        mu *= 0.03125f;
        float var = 0.f;
        #pragma unroll
        for (int c = 0; c < 32; c++) { float d = xn[c] - mu; var += d * d; }
        float rs = rsqrtf(var * 0.03125f + LN_EPS);
        __syncthreads();   // weights staged
        #pragma unroll
        for (int c = 0; c < 32; c++) xn[c] = (xn[c] - mu) * rs * sg1[c] + sbe1[c];
    }

    // ---- q = leaky(xn @ Wq + bq) * SCALE ----
    float q[32];
    {
        unsigned long long acc[16];
        #pragma unroll
        for (int i = 0; i < 16; i++) acc[i] = 0ull;
        #pragma unroll 4
        for (int k = 0; k < 32; k++) {
            unsigned long long xk2 = pk2(xn[k], xn[k]);
            const ulonglong2* wr = reinterpret_cast<const ulonglong2*>(&sWq[k * 32]);
            #pragma unroll
            for (int j = 0; j < 8; j++) {
                ulonglong2 u = wr[j];
                fma2(acc[2*j+0], xk2, u.x);
                fma2(acc[2*j+1], xk2, u.y);
            }
        }
        #pragma unroll
        for (int i = 0; i < 16; i++) {
            float a0, a1; upk2(acc[i], a0, a1);
            q[2*i+0] = leaky_f(a0 + sbq[2*i+0]) * ATTN_SCALE;
            q[2*i+1] = leaky_f(a1 + sbq[2*i+1]) * ATTN_SCALE;
        }
    }

    // ---- k, v = leaky(xn @ Wkv + bkv), stored transposed [c][m] ----
    #pragma unroll
    for (int hh = 0; hh < 2; hh++) {
        unsigned long long acc[16];
        #pragma unroll
        for (int i = 0; i < 16; i++) acc[i] = 0ull;
        #pragma unroll 4
        for (int k = 0; k < 32; k++) {
            unsigned long long xk2 = pk2(xn[k], xn[k]);
            const ulonglong2* wr =
                reinterpret_cast<const ulonglong2*>(&sWkv[k * 64 + hh * 32]);
            #pragma unroll
            for (int j = 0; j < 8; j++) {
                ulonglong2 u = wr[j];
                fma2(acc[2*j+0], xk2, u.x);
                fma2(acc[2*j+1], xk2, u.y);
            }
        }
        float* dst = hh ? vs[wloc] : ks[wloc];
        #pragma unroll
        for (int i = 0; i < 16; i++) {
            float a0, a1; upk2(acc[i], a0, a1);
            dst[(2*i+0) * 64 + tw] = leaky_f(a0 + sbkv[hh * 32 + 2*i+0]);
            dst[(2*i+1) * 64 + tw] = leaky_f(a1 + sbkv[hh * 32 + 2*i+1]);
        }
    }
    __syncthreads();

    // ---- scores (4 passes of 16 columns to cap live registers) ----
    float a[64];
    {
        const float4* brow4 = reinterpret_cast<const float4*>(&g_bias[tw * 64]);
        #pragma unroll
        for (int h4 = 0; h4 < 4; h4++) {
            unsigned long long aa[8];
            #pragma unroll
            for (int i = 0; i < 8; i++) aa[i] = 0ull;
            #pragma unroll 4
            for (int c = 0; c < 32; c++) {
                unsigned long long q2 = pk2(q[c], q[c]);
                const ulonglong2* kr =
                    reinterpret_cast<const ulonglong2*>(&ks[wloc][c * 64 + h4 * 16]);
                #pragma unroll
                for (int j = 0; j < 4; j++) {
                    ulonglong2 u = kr[j];
                    fma2(aa[2*j+0], q2, u.x);
                    fma2(aa[2*j+1], q2, u.y);
                }
            }
            #pragma unroll
            for (int i = 0; i < 4; i++) {
                float4 bv = brow4[h4 * 4 + i];
                float a0, a1, b0, b1;
                upk2(aa[2*i+0], a0, a1);
                upk2(aa[2*i+1], b0, b1);
                a[h4*16 + 4*i + 0] = a0 + bv.x;
                a[h4*16 + 4*i + 1] = a1 + bv.y;
                a[h4*16 + 4*i + 2] = b0 + bv.z;
                a[h4*16 + 4*i + 3] = b1 + bv.w;
            }
        }
    }

    // ---- softmax (pack exp on the fly; normalization deferred) ----
    float mx = a[0];
    #pragma unroll
    for (int m = 1; m < 64; m++) mx = fmaxf(mx, a[m]);
    float sum = 0.f;
    unsigned long long ap[32];
    #pragma unroll
    for (int i = 0; i < 32; i++) {
        float e0 = __expf(a[2*i+0] - mx);
        float e1 = __expf(a[2*i+1] - mx);
        sum += e0 + e1;
        ap[i] = pk2(e0, e1);
    }
    float inv = 1.f / sum;

    // ---- fused AV + proj:  pa += (attn@v)[c] * Wp[c][:] ----
    unsigned long long pa[16];
    #pragma unroll
    for (int i = 0; i < 16; i++) pa[i] = 0ull;
    #pragma unroll 2
    for (int c = 0; c < 32; c++) {
        unsigned long long acc0 = 0ull, acc1 = 0ull;
        const ulonglong2* vr = reinterpret_cast<const ulonglong2*>(&vs[wloc][c * 64]);
        #pragma unroll
        for (int j = 0; j < 16; j++) {
            ulonglong2 u = vr[j];
            fma2(acc0, ap[2*j+0], u.x);
            fma2(acc1, ap[2*j+1], u.y);
        }
        float l0, h0, l1, h1;
        upk2(acc0, l0, h0); upk2(acc1, l1, h1);
        float oc = ((l0 + h0) + (l1 + h1)) * inv;
        unsigned long long o2 = pk2(oc, oc);
        const ulonglong2* wr = reinterpret_cast<const ulonglong2*>(&sWp[c * 32]);
        #pragma unroll
        for (int j = 0; j < 8; j++) {
            ulonglong2 u = wr[j];
            fma2(pa[2*j+0], o2, u.x);
            fma2(pa[2*j+1], o2, u.y);
        }
    }

    // ---- residual + store ----
    const float4* xp2 = reinterpret_cast<const float4*>(x + base);
    float4* op = reinterpret_cast<float4*>(out + base);
    #pragma unroll
    for (int i = 0; i < 8; i++) {
        float4 xv = xp2[i];
        float a0, a1, b0, b1;
        upk2(pa[2*i+0], a0, a1);
        upk2(pa[2*i+1], b0, b1);
        float4 r;
        r.x = xv.x + a0 + sbp[4*i+0];
        r.y = xv.y + a1 + sbp[4*i+1];
        r.z = xv.z + b0 + sbp[4*i+2];
        r.w = xv.w + b1 + sbp[4*i+3];
        op[i] = r;
    }
}

// ---- KB1: LN2 + W1 + gelu  ->  g_h [chunk][token][8] --------------------------
__global__ __launch_bounds__(256) void kb1(
    const float* __restrict__ x2,
    const float* __restrict__ g2, const float* __restrict__ be2,
    const float* __restrict__ W1, const float* __restrict__ b1m)
{
    __shared__ __align__(16) float sW1[4096];
    __shared__ float sb1[128], sg[32], sb[32];
    const int t = threadIdx.x;
    {
        const float4* W14 = reinterpret_cast<const float4*>(W1);
        float4* s4 = reinterpret_cast<float4*>(sW1);
        for (int i = t; i < 1024; i += 256) s4[i] = W14[i];
    }
    if (t < 128) sb1[t] = b1m[t];
    if (t < 32) { sg[t] = g2[t]; sb[t] = be2[t]; }

    const int tok = blockIdx.x * 256 + t;
    float y[32];
    const float4* xp = reinterpret_cast<const float4*>(x2 + tok * 32);
    #pragma unroll
    for (int i = 0; i < 8; i++) {
        float4 v4 = xp[i];
        y[4*i+0] = v4.x; y[4*i+1] = v4.y; y[4*i+2] = v4.z; y[4*i+3] = v4.w;
    }
    float mu = 0.f;
    #pragma unroll
    for (int c = 0; c < 32; c++) mu += y[c];
    mu *= 0.03125f;
    float var = 0.f;
    #pragma unroll
    for (int c = 0; c < 32; c++) { float d = y[c] - mu; var += d * d; }
    float rs = rsqrtf(var * 0.03125f + LN_EPS);
    __syncthreads();
    #pragma unroll
    for (int c = 0; c < 32; c++) y[c] = (y[c] - mu) * rs * sg[c] + sb[c];

    #pragma unroll
    for (int p = 0; p < 4; p++) {
        unsigned long long acc[16];
        #pragma unroll
        for (int i = 0; i < 16; i++) acc[i] = 0ull;
        #pragma unroll 4
        for (int c = 0; c < 32; c++) {
            unsigned long long y2 = pk2(y[c], y[c]);
            const ulonglong2* wr =
                reinterpret_cast<const ulonglong2*>(&sW1[c * 128 + p * 32]);
            #pragma unroll
            for (int j = 0; j < 8; j++) {
                ulonglong2 u = wr[j];
                fma2(acc[2*j+0], y2, u.x);
                fma2(acc[2*j+1], y2, u.y);
            }
        }
        #pragma unroll
        for (int i = 0; i < 8; i++) {
            float v0, v1, v2, v3;
            upk2(acc[2*i+0], v0, v1);
            upk2(acc[2*i+1], v2, v3);
            int jb = p * 32 + 4 * i;
            float4 r;
            r.x = gelu_fast(v0 + sb1[jb+0]);
            r.y = gelu_fast(v1 + sb1[jb+1]);
            r.z = gelu_fast(v2 + sb1[jb+2]);
            r.w = gelu_fast(v3 + sb1[jb+3]);
            // g_h layout [chunk16][token][8]
            __stcs(reinterpret_cast<float4*>(
                &g_h[((size_t)(jb >> 3) * 524288 + tok) * 8 + (jb & 7)]), r);
        }
    }
}

// ---- KCONV: depthwise 3x3 + gelu for ONE 8-ch chunk per block  -> g_h2 (fp16) --
// Grid: [2 batch][16 chunk][32 ty][16 tx]; block 256 thr; tile 32x16 px;
// each thread: 2 vertically-adjacent pixels x 8 channels.
__global__ __launch_bounds__(256) void kconv(
    const float* __restrict__ dwk, const float* __restrict__ dwb)
{
    __shared__ float sp[8 * 648];     // 8 planes of 18 x 36 (stride 36)
    __shared__ float sk[72], skb[8];

    const int t  = threadIdx.x;
    const int bb = blockIdx.x;
    const int b     = bb >> 13;
    const int chunk = (bb >> 9) & 15;
    const int ty0   = ((bb >> 4) & 31) * 16;
    const int tx0   = (bb & 15) * 32;
    const int plane = b * 262144;

    if (t < 72) sk[t] = dwk[(t >> 3) * 128 + chunk * 8 + (t & 7)];
    if (t < 8)  skb[t] = dwb[chunk * 8 + t];

    // halo 18 x 34, 8 channels (32B per position = 2 float4)
    const size_t cbase = (size_t)chunk * 524288 + plane;
    for (int i = t; i < 1224; i += 256) {
        int pos = i >> 1, half = i & 1;
        int pr = pos / 34, pc = pos - pr * 34;
        int gy = ty0 - 1 + pr, gx = tx0 - 1 + pc;
        float4 v = make_float4(0.f, 0.f, 0.f, 0.f);
        if ((unsigned)gy < 512u && (unsigned)gx < 512u)
            v = *reinterpret_cast<const float4*>(
                &g_h[(cbase + gy * 512 + gx) * 8 + half * 4]);
        float* d = &sp[(half * 4) * 648 + pr * 36 + pc];
        d[0]        = v.x;
        d[648]      = v.y;
        d[2 * 648]  = v.z;
        d[3 * 648]  = v.w;
    }
    __syncthreads();

    const int cx  = t & 31;
    const int ry2 = (t >> 5) * 2;            // rows ry2, ry2+1 of the tile
    float o0[8], o1[8];
    #pragma unroll
    for (int c = 0; c < 8; c++) {
        const float* pl = &sp[c * 648 + ry2 * 36 + cx];
        float r0[3], r1[3], r2[3], r3[3];
        #pragma unroll
        for (int d = 0; d < 3; d++) {
            r0[d] = pl[d];
            r1[d] = pl[36 + d];
            r2[d] = pl[72 + d];
            r3[d] = pl[108 + d];
        }
        float s0 = 0.f, s1 = 0.f;
        #pragma unroll
        for (int kx = 0; kx < 3; kx++) {
            float k0 = sk[(0 + kx) * 8 + c];
            float k1 = sk[(3 + kx) * 8 + c];
            float k2 = sk[(6 + kx) * 8 + c];
            s0 += r0[kx] * k0 + r1[kx] * k1 + r2[kx] * k2;
            s1 += r1[kx] * k0 + r2[kx] * k1 + r3[kx] * k2;
        }
        o0[c] = gelu_exact(s0 + skb[c]);
        o1[c] = gelu_exact(s1 + skb[c]);
    }

    const size_t tok0 = cbase + (size_t)(ty0 + ry2) * 512 + tx0 + cx;
    {
        __half2 p0[4] = {
            __floats2half2_rn(o0[0], o0[1]), __floats2half2_rn(o0[2], o0[3]),
            __floats2half2_rn(o0[4], o0[5]), __floats2half2_rn(o0[6], o0[7])};
        __half2 p1[4] = {
            __floats2half2_rn(o1[0], o1[1]), __floats2half2_rn(o1[2], o1[3]),
            __floats2half2_rn(o1[4], o1[5]), __floats2half2_rn(o1[6], o1[7])};
        *reinterpret_cast<uint4*>(&g_h2[tok0 * 8]) =
            *reinterpret_cast<const uint4*>(p0);
        *reinterpret_cast<uint4*>(&g_h2[(tok0 + 512) * 8]) =
            *reinterpret_cast<const uint4*>(p1);
    }
}

// ---- KW2: out += conv_hidden(fp16) @ W2 + b2  (token-parallel) -----------------
__global__ __launch_bounds__(256) void kw2(
    const float* __restrict__ W2, const float* __restrict__ b2m,
    float* __restrict__ out)
{
    __shared__ __align__(16) float sW2[4096];
    __shared__ float sb2[32];
    const int t = threadIdx.x;
    {
        const float4* W24 = reinterpret_cast<const float4*>(W2);
        float4* s4 = reinterpret_cast<float4*>(sW2);
        for (int i = t; i < 1024; i += 256) s4[i] = W24[i];
    }
    if (t < 32) sb2[t] = b2m[t];
    __syncthreads();

    const int tok = blockIdx.x * 256 + t;

    unsigned long long acc[16];
    #pragma unroll
    for (int i = 0; i < 16; i++) acc[i] = 0ull;

    #pragma unroll 2
    for (int chunk = 0; chunk < 16; chunk++) {
        uint4 raw = *reinterpret_cast<const uint4*>(
            &g_h2[((size_t)chunk * 524288 + tok) * 8]);
        const __half2* hh = reinterpret_cast<const __half2*>(&raw);
        float2 f0 = __half22float2(hh[0]);
        float2 f1 = __half22float2(hh[1]);
        float2 f2 = __half22float2(hh[2]);
        float2 f3 = __half22float2(hh[3]);
        float hv[8] = {f0.x, f0.y, f1.x, f1.y, f2.x, f2.y, f3.x, f3.y};
        #pragma unroll
        for (int c = 0; c < 8; c++) {
            const int ch = chunk * 8 + c;
            unsigned long long s2 = pk2(hv[c], hv[c]);
            const ulonglong2* wr = reinterpret_cast<const ulonglong2*>(&sW2[ch * 32]);
            #pragma unroll
            for (int j = 0; j < 8; j++) {
                ulonglong2 u = wr[j];
                fma2(acc[2*j+0], s2, u.x);
                fma2(acc[2*j+1], s2, u.y);
            }
        }
    }

    const int base = tok * 32;
    #pragma unroll
    for (int i = 0; i < 8; i++) {
        float4 xv = *reinterpret_cast<const float4*>(out + base + 4 * i);
        float a0, a1, b0, b1;
        upk2(acc[2*i+0], a0, a1);
        upk2(acc[2*i+1], b0, b1);
        float4 r;
        r.x = xv.x + a0 + sb2[4*i+0];
        r.y = xv.y + a1 + sb2[4*i+1];
        r.z = xv.z + b0 + sb2[4*i+2];
        r.w = xv.w + b1 + sb2[4*i+3];
        *reinterpret_cast<float4*>(out + base + 4 * i) = r;
    }
}

// ---- launch -------------------------------------------------------------------
extern "C" void kernel_launch(void* const* d_in, const int* in_sizes, int n_in,
                              void* d_out, int out_size) {
    const float* x          = (const float*)d_in[0];
    const float* g1         = (const float*)d_in[1];
    const float* beta1      = (const float*)d_in[2];
    const float* Wq         = (const float*)d_in[3];
    const float* bq         = (const float*)d_in[4];
    const float* Wkv        = (const float*)d_in[5];
    const float* bkv        = (const float*)d_in[6];
    const float* bias_table = (const float*)d_in[7];
    const float* Wp         = (const float*)d_in[8];
    const float* bp         = (const float*)d_in[9];
    const float* g2         = (const float*)d_in[10];
    const float* beta2      = (const float*)d_in[11];
    const float* W1         = (const float*)d_in[12];
    const float* b1m        = (const float*)d_in[13];
    const float* dw_k       = (const float*)d_in[14];
    const float* dw_b       = (const float*)d_in[15];
    const float* W2         = (const float*)d_in[16];
    const float* b2m        = (const float*)d_in[17];
    const int*   rel_idx    = (const int*)d_in[18];
    float* out = (float*)d_out;

    kbias<<<16, 256>>>(bias_table, rel_idx);
    ka_attn<<<4096, 128>>>(x, g1, beta1, Wq, bq, Wkv, bkv, Wp, bp, out);
    kb1<<<2048, 256>>>(out, g2, beta2, W1, b1m);
    kconv<<<16384, 256>>>(dw_k, dw_b);
    kw2<<<2048, 256>>>(W2, b2m, out);
}

// round 17
// speedup vs baseline: 1.2385x; 1.0535x over previous
#include <cuda_runtime.h>
#include <cuda_fp16.h>

#define SLOPE 0.3f
#define ATTN_SCALE 0.17677669529663687f   // 32^-0.5
#define LN_EPS 1e-3f

// ---- scratch (no allocs allowed) -------------------------------------------
__device__ float g_bias[4096];        // bias_table[rel_idx]  (64x64)
// hidden scratch h (pre-conv), layout [chunk16][token(2*512*512)][8ch], fp16
__device__ __half g_h[67108864];
// conv output h2, same layout, fp16
__device__ __half g_h2[67108864];

// ---- packed f32x2 helpers ----------------------------------------------------
__device__ __forceinline__ unsigned long long pk2(float a, float b) {
    unsigned long long r;
    asm("mov.b64 %0, {%1, %2};" : "=l"(r)
        : "r"(__float_as_uint(a)), "r"(__float_as_uint(b)));
    return r;
}
__device__ __forceinline__ void upk2(unsigned long long v, float& a, float& b) {
    unsigned int x, y;
    asm("mov.b64 {%0, %1}, %2;" : "=r"(x), "=r"(y) : "l"(v));
    a = __uint_as_float(x); b = __uint_as_float(y);
}
__device__ __forceinline__ void fma2(unsigned long long& d,
                                     unsigned long long a, unsigned long long b) {
    asm("fma.rn.f32x2 %0, %1, %2, %0;" : "+l"(d) : "l"(a), "l"(b));
}
// exact gelu via libdevice erff — fewer live registers (measured best in kconv)
__device__ __forceinline__ float gelu_exact(float z) {
    return 0.5f * z * (1.0f + erff(z * 0.70710678118654752f));
}
// A&S 7.1.26 erf gelu, |abs err| < 1.5e-7 — fewer ALU ops (used in kb1)
__device__ __forceinline__ float gelu_fast(float z) {
    float x = fabsf(z) * 0.70710678118654752f;
    float t = __fdividef(1.0f, fmaf(0.3275911f, x, 1.0f));
    float p = t * fmaf(t, fmaf(t, fmaf(t, fmaf(t, 1.061405429f, -1.453152027f),
                                       1.421413741f), -0.284496736f), 0.254829592f);
    float e = __expf(-x * x);
    float er = copysignf(fmaf(-p, e, 1.0f), z);
    return 0.5f * z * (1.0f + er);
}
__device__ __forceinline__ float leaky_f(float z) {
    return z >= 0.f ? z : SLOPE * z;
}

// ---- K0: gather relative-position bias --------------------------------------
__global__ void kbias(const float* __restrict__ table, const int* __restrict__ idx) {
    int i = blockIdx.x * 256 + threadIdx.x;
    if (i < 4096) g_bias[i] = table[idx[i]];
}

// ---- KA: fused LN1 + window attention + proj + residual  ->  x2 (= d_out) ---
// 1 block = 2 windows (128 threads), 1 thread = 1 token.
__global__ __launch_bounds__(128) void ka_attn(
    const float* __restrict__ x,
    const float* __restrict__ g1, const float* __restrict__ be1,
    const float* __restrict__ Wq, const float* __restrict__ bq,
    const float* __restrict__ Wkv, const float* __restrict__ bkv,
    const float* __restrict__ Wp, const float* __restrict__ bp,
    float* __restrict__ out)
{
    __shared__ __align__(16) float sWq[1024];
    __shared__ __align__(16) float sWkv[2048];
    __shared__ __align__(16) float sWp[1024];
    __shared__ __align__(16) float ks[2][2048];   // k transposed [c][m], per window
    __shared__ __align__(16) float vs[2][2048];   // v transposed [c][m], per window
    __shared__ float sbq[32], sbp[32], sg1[32], sbe1[32], sbkv[64];

    const int t = threadIdx.x;
    {   // vectorized weight staging
        const float4* Wq4  = reinterpret_cast<const float4*>(Wq);
        const float4* Wp4  = reinterpret_cast<const float4*>(Wp);
        const float4* Wkv4 = reinterpret_cast<const float4*>(Wkv);
        float4* sq4 = reinterpret_cast<float4*>(sWq);
        float4* sp4 = reinterpret_cast<float4*>(sWp);
        float4* sk4 = reinterpret_cast<float4*>(sWkv);
        for (int i = t; i < 256; i += 128) { sq4[i] = Wq4[i]; sp4[i] = Wp4[i]; }
        for (int i = t; i < 512; i += 128) sk4[i] = Wkv4[i];
        if (t < 32) { sbq[t] = bq[t]; sbp[t] = bp[t]; sg1[t] = g1[t]; sbe1[t] = be1[t]; }
        if (t < 64) sbkv[t] = bkv[t];
    }

    const int wloc = t >> 6;                      // which of the 2 windows
    const int tw   = t & 63;                      // token within window
    const int w  = blockIdx.x * 2 + wloc;
    const int b  = w >> 12;
    const int wy = (w >> 6) & 63;
    const int wx = w & 63;
    const int py = wy * 8 + (tw >> 3);
    const int px = wx * 8 + (tw & 7);
    const int base = (b * 262144 + py * 512 + px) * 32;

    // ---- LN1 ----
    float xn[32];
    {
        const float4* xp = reinterpret_cast<const float4*>(x + base);
        #pragma unroll
        for (int i = 0; i < 8; i++) {
            float4 v4 = xp[i];
            xn[4*i+0] = v4.x; xn[4*i+1] = v4.y; xn[4*i+2] = v4.z; xn[4*i+3] = v4.w;
        }
        float mu = 0.f;
        #pragma unroll
        for (int c = 0; c < 32; c++) mu += xn[c];
        mu *= 0.03125f;
        float var = 0.f;
        #pragma unroll
        for (int c = 0; c < 32; c++) { float d = xn[c] - mu; var += d * d; }
        float rs = rsqrtf(var * 0.03125f + LN_EPS);
        __syncthreads();   // weights staged
        #pragma unroll
        for (int c = 0; c < 32; c++) xn[c] = (xn[c] - mu) * rs * sg1[c] + sbe1[c];
    }

    // ---- q = leaky(xn @ Wq + bq) * SCALE ----
    float q[32];
    {
        unsigned long long acc[16];
        #pragma unroll
        for (int i = 0; i < 16; i++) acc[i] = 0ull;
        #pragma unroll 4
        for (int k = 0; k < 32; k++) {
            unsigned long long xk2 = pk2(xn[k], xn[k]);
            const ulonglong2* wr = reinterpret_cast<const ulonglong2*>(&sWq[k * 32]);
            #pragma unroll
            for (int j = 0; j < 8; j++) {
                ulonglong2 u = wr[j];
                fma2(acc[2*j+0], xk2, u.x);
                fma2(acc[2*j+1], xk2, u.y);
            }
        }
        #pragma unroll
        for (int i = 0; i < 16; i++) {
            float a0, a1; upk2(acc[i], a0, a1);
            q[2*i+0] = leaky_f(a0 + sbq[2*i+0]) * ATTN_SCALE;
            q[2*i+1] = leaky_f(a1 + sbq[2*i+1]) * ATTN_SCALE;
        }
    }

    // ---- k, v = leaky(xn @ Wkv + bkv), stored transposed [c][m] ----
    #pragma unroll
    for (int hh = 0; hh < 2; hh++) {
        unsigned long long acc[16];
        #pragma unroll
        for (int i = 0; i < 16; i++) acc[i] = 0ull;
        #pragma unroll 4
        for (int k = 0; k < 32; k++) {
            unsigned long long xk2 = pk2(xn[k], xn[k]);
            const ulonglong2* wr =
                reinterpret_cast<const ulonglong2*>(&sWkv[k * 64 + hh * 32]);
            #pragma unroll
            for (int j = 0; j < 8; j++) {
                ulonglong2 u = wr[j];
                fma2(acc[2*j+0], xk2, u.x);
                fma2(acc[2*j+1], xk2, u.y);
            }
        }
        float* dst = hh ? vs[wloc] : ks[wloc];
        #pragma unroll
        for (int i = 0; i < 16; i++) {
            float a0, a1; upk2(acc[i], a0, a1);
            dst[(2*i+0) * 64 + tw] = leaky_f(a0 + sbkv[hh * 32 + 2*i+0]);
            dst[(2*i+1) * 64 + tw] = leaky_f(a1 + sbkv[hh * 32 + 2*i+1]);
        }
    }
    __syncthreads();

    // ---- scores (4 passes of 16 columns to cap live registers) ----
    float a[64];
    {
        const float4* brow4 = reinterpret_cast<const float4*>(&g_bias[tw * 64]);
        #pragma unroll
        for (int h4 = 0; h4 < 4; h4++) {
            unsigned long long aa[8];
            #pragma unroll
            for (int i = 0; i < 8; i++) aa[i] = 0ull;
            #pragma unroll 4
            for (int c = 0; c < 32; c++) {
                unsigned long long q2 = pk2(q[c], q[c]);
                const ulonglong2* kr =
                    reinterpret_cast<const ulonglong2*>(&ks[wloc][c * 64 + h4 * 16]);
                #pragma unroll
                for (int j = 0; j < 4; j++) {
                    ulonglong2 u = kr[j];
                    fma2(aa[2*j+0], q2, u.x);
                    fma2(aa[2*j+1], q2, u.y);
                }
            }
            #pragma unroll
            for (int i = 0; i < 4; i++) {
                float4 bv = brow4[h4 * 4 + i];
                float a0, a1, b0, b1;
                upk2(aa[2*i+0], a0, a1);
                upk2(aa[2*i+1], b0, b1);
                a[h4*16 + 4*i + 0] = a0 + bv.x;
                a[h4*16 + 4*i + 1] = a1 + bv.y;
                a[h4*16 + 4*i + 2] = b0 + bv.z;
                a[h4*16 + 4*i + 3] = b1 + bv.w;
            }
        }
    }

    // ---- softmax (pack exp on the fly; normalization deferred) ----
    float mx = a[0];
    #pragma unroll
    for (int m = 1; m < 64; m++) mx = fmaxf(mx, a[m]);
    float sum = 0.f;
    unsigned long long ap[32];
    #pragma unroll
    for (int i = 0; i < 32; i++) {
        float e0 = __expf(a[2*i+0] - mx);
        float e1 = __expf(a[2*i+1] - mx);
        sum += e0 + e1;
        ap[i] = pk2(e0, e1);
    }
    float inv = 1.f / sum;

    // ---- fused AV + proj:  pa += (attn@v)[c] * Wp[c][:] ----
    unsigned long long pa[16];
    #pragma unroll
    for (int i = 0; i < 16; i++) pa[i] = 0ull;
    #pragma unroll 2
    for (int c = 0; c < 32; c++) {
        unsigned long long acc0 = 0ull, acc1 = 0ull;
        const ulonglong2* vr = reinterpret_cast<const ulonglong2*>(&vs[wloc][c * 64]);
        #pragma unroll
        for (int j = 0; j < 16; j++) {
            ulonglong2 u = vr[j];
            fma2(acc0, ap[2*j+0], u.x);
            fma2(acc1, ap[2*j+1], u.y);
        }
        float l0, h0, l1, h1;
        upk2(acc0, l0, h0); upk2(acc1, l1, h1);
        float oc = ((l0 + h0) + (l1 + h1)) * inv;
        unsigned long long o2 = pk2(oc, oc);
        const ulonglong2* wr = reinterpret_cast<const ulonglong2*>(&sWp[c * 32]);
        #pragma unroll
        for (int j = 0; j < 8; j++) {
            ulonglong2 u = wr[j];
            fma2(pa[2*j+0], o2, u.x);
            fma2(pa[2*j+1], o2, u.y);
        }
    }

    // ---- residual + store ----
    const float4* xp2 = reinterpret_cast<const float4*>(x + base);
    float4* op = reinterpret_cast<float4*>(out + base);
    #pragma unroll
    for (int i = 0; i < 8; i++) {
        float4 xv = xp2[i];
        float a0, a1, b0, b1;
        upk2(pa[2*i+0], a0, a1);
        upk2(pa[2*i+1], b0, b1);
        float4 r;
        r.x = xv.x + a0 + sbp[4*i+0];
        r.y = xv.y + a1 + sbp[4*i+1];
        r.z = xv.z + b0 + sbp[4*i+2];
        r.w = xv.w + b1 + sbp[4*i+3];
        op[i] = r;
    }
}

// ---- KB1: LN2 + W1 + gelu  ->  g_h (fp16) [chunk][token][8] -------------------
__global__ __launch_bounds__(256) void kb1(
    const float* __restrict__ x2,
    const float* __restrict__ g2, const float* __restrict__ be2,
    const float* __restrict__ W1, const float* __restrict__ b1m)
{
    __shared__ __align__(16) float sW1[4096];
    __shared__ float sb1[128], sg[32], sb[32];
    const int t = threadIdx.x;
    {
        const float4* W14 = reinterpret_cast<const float4*>(W1);
        float4* s4 = reinterpret_cast<float4*>(sW1);
        for (int i = t; i < 1024; i += 256) s4[i] = W14[i];
    }
    if (t < 128) sb1[t] = b1m[t];
    if (t < 32) { sg[t] = g2[t]; sb[t] = be2[t]; }

    const int tok = blockIdx.x * 256 + t;
    float y[32];
    const float4* xp = reinterpret_cast<const float4*>(x2 + tok * 32);
    #pragma unroll
    for (int i = 0; i < 8; i++) {
        float4 v4 = xp[i];
        y[4*i+0] = v4.x; y[4*i+1] = v4.y; y[4*i+2] = v4.z; y[4*i+3] = v4.w;
    }
    float mu = 0.f;
    #pragma unroll
    for (int c = 0; c < 32; c++) mu += y[c];
    mu *= 0.03125f;
    float var = 0.f;
    #pragma unroll
    for (int c = 0; c < 32; c++) { float d = y[c] - mu; var += d * d; }
    float rs = rsqrtf(var * 0.03125f + LN_EPS);
    __syncthreads();
    #pragma unroll
    for (int c = 0; c < 32; c++) y[c] = (y[c] - mu) * rs * sg[c] + sb[c];

    #pragma unroll
    for (int p = 0; p < 4; p++) {
        unsigned long long acc[16];
        #pragma unroll
        for (int i = 0; i < 16; i++) acc[i] = 0ull;
        #pragma unroll 4
        for (int c = 0; c < 32; c++) {
            unsigned long long y2 = pk2(y[c], y[c]);
            const ulonglong2* wr =
                reinterpret_cast<const ulonglong2*>(&sW1[c * 128 + p * 32]);
            #pragma unroll
            for (int j = 0; j < 8; j++) {
                ulonglong2 u = wr[j];
                fma2(acc[2*j+0], y2, u.x);
                fma2(acc[2*j+1], y2, u.y);
            }
        }
        // 32 channels = 4 chunks of 8; one 16B fp16 store per chunk
        #pragma unroll
        for (int g = 0; g < 4; g++) {
            float v[8];
            #pragma unroll
            for (int i = 0; i < 4; i++)
                upk2(acc[4*g + i], v[2*i], v[2*i+1]);
            const int jb = p * 32 + 8 * g;           // first channel of chunk
            __half2 hp[4];
            #pragma unroll
            for (int i = 0; i < 4; i++)
                hp[i] = __floats2half2_rn(gelu_fast(v[2*i]   + sb1[jb + 2*i]),
                                          gelu_fast(v[2*i+1] + sb1[jb + 2*i+1]));
            __stcs(reinterpret_cast<float4*>(
                       &g_h[((size_t)(jb >> 3) * 524288 + tok) * 8]),
                   *reinterpret_cast<const float4*>(hp));
        }
    }
}

// ---- KCONV: depthwise 3x3 + gelu for ONE 8-ch chunk per block  -> g_h2 (fp16) --
// Grid: [2 batch][16 chunk][32 ty][16 tx]; block 256 thr; tile 32x16 px;
// each thread: 2 vertically-adjacent pixels x 8 channels.
__global__ __launch_bounds__(256) void kconv(
    const float* __restrict__ dwk, const float* __restrict__ dwb)
{
    __shared__ float sp[8 * 648];     // 8 planes of 18 x 36 (stride 36)
    __shared__ float sk[72], skb[8];

    const int t  = threadIdx.x;
    const int bb = blockIdx.x;
    const int b     = bb >> 13;
    const int chunk = (bb >> 9) & 15;
    const int ty0   = ((bb >> 4) & 31) * 16;
    const int tx0   = (bb & 15) * 32;
    const int plane = b * 262144;

    if (t < 72) sk[t] = dwk[(t >> 3) * 128 + chunk * 8 + (t & 7)];
    if (t < 8)  skb[t] = dwb[chunk * 8 + t];

    // halo 18 x 34, 8 fp16 channels (16B per position = 1 uint4)
    const size_t cbase = (size_t)chunk * 524288 + plane;
    for (int i = t; i < 612; i += 256) {
        int pr = i / 34, pc = i - pr * 34;
        int gy = ty0 - 1 + pr, gx = tx0 - 1 + pc;
        float f[8] = {0.f, 0.f, 0.f, 0.f, 0.f, 0.f, 0.f, 0.f};
        if ((unsigned)gy < 512u && (unsigned)gx < 512u) {
            uint4 raw = *reinterpret_cast<const uint4*>(
                &g_h[(cbase + gy * 512 + gx) * 8]);
            const __half2* hh = reinterpret_cast<const __half2*>(&raw);
            #pragma unroll
            for (int j = 0; j < 4; j++) {
                float2 fj = __half22float2(hh[j]);
                f[2*j] = fj.x; f[2*j+1] = fj.y;
            }
        }
        float* d = &sp[pr * 36 + pc];
        #pragma unroll
        for (int c = 0; c < 8; c++) d[c * 648] = f[c];
    }
    __syncthreads();

    const int cx  = t & 31;
    const int ry2 = (t >> 5) * 2;            // rows ry2, ry2+1 of the tile
    float o0[8], o1[8];
    #pragma unroll
    for (int c = 0; c < 8; c++) {
        const float* pl = &sp[c * 648 + ry2 * 36 + cx];
        float r0[3], r1[3], r2[3], r3[3];
        #pragma unroll
        for (int d = 0; d < 3; d++) {
            r0[d] = pl[d];
            r1[d] = pl[36 + d];
            r2[d] = pl[72 + d];
            r3[d] = pl[108 + d];
        }
        float s0 = 0.f, s1 = 0.f;
        #pragma unroll
        for (int kx = 0; kx < 3; kx++) {
            float k0 = sk[(0 + kx) * 8 + c];
            float k1 = sk[(3 + kx) * 8 + c];
            float k2 = sk[(6 + kx) * 8 + c];
            s0 += r0[kx] * k0 + r1[kx] * k1 + r2[kx] * k2;
            s1 += r1[kx] * k0 + r2[kx] * k1 + r3[kx] * k2;
        }
        o0[c] = gelu_exact(s0 + skb[c]);
        o1[c] = gelu_exact(s1 + skb[c]);
    }

    const size_t tok0 = cbase + (size_t)(ty0 + ry2) * 512 + tx0 + cx;
    {
        __half2 p0[4] = {
            __floats2half2_rn(o0[0], o0[1]), __floats2half2_rn(o0[2], o0[3]),
            __floats2half2_rn(o0[4], o0[5]), __floats2half2_rn(o0[6], o0[7])};
        __half2 p1[4] = {
            __floats2half2_rn(o1[0], o1[1]), __floats2half2_rn(o1[2], o1[3]),
            __floats2half2_rn(o1[4], o1[5]), __floats2half2_rn(o1[6], o1[7])};
        *reinterpret_cast<uint4*>(&g_h2[tok0 * 8]) =
            *reinterpret_cast<const uint4*>(p0);
        *reinterpret_cast<uint4*>(&g_h2[(tok0 + 512) * 8]) =
            *reinterpret_cast<const uint4*>(p1);
    }
}

// ---- KW2: out += conv_hidden(fp16) @ W2 + b2  (token-parallel) -----------------
__global__ __launch_bounds__(256) void kw2(
    const float* __restrict__ W2, const float* __restrict__ b2m,
    float* __restrict__ out)
{
    __shared__ __align__(16) float sW2[4096];
    __shared__ float sb2[32];
    const int t = threadIdx.x;
    {
        const float4* W24 = reinterpret_cast<const float4*>(W2);
        float4* s4 = reinterpret_cast<float4*>(sW2);
        for (int i = t; i < 1024; i += 256) s4[i] = W24[i];
    }
    if (t < 32) sb2[t] = b2m[t];
    __syncthreads();

    const int tok = blockIdx.x * 256 + t;

    unsigned long long acc[16];
    #pragma unroll
    for (int i = 0; i < 16; i++) acc[i] = 0ull;

    #pragma unroll 2
    for (int chunk = 0; chunk < 16; chunk++) {
        uint4 raw = *reinterpret_cast<const uint4*>(
            &g_h2[((size_t)chunk * 524288 + tok) * 8]);
        const __half2* hh = reinterpret_cast<const __half2*>(&raw);
        float2 f0 = __half22float2(hh[0]);
        float2 f1 = __half22float2(hh[1]);
        float2 f2 = __half22float2(hh[2]);
        float2 f3 = __half22float2(hh[3]);
        float hv[8] = {f0.x, f0.y, f1.x, f1.y, f2.x, f2.y, f3.x, f3.y};
        #pragma unroll
        for (int c = 0; c < 8; c++) {
            const int ch = chunk * 8 + c;
            unsigned long long s2 = pk2(hv[c], hv[c]);
            const ulonglong2* wr = reinterpret_cast<const ulonglong2*>(&sW2[ch * 32]);
            #pragma unroll
            for (int j = 0; j < 8; j++) {
                ulonglong2 u = wr[j];
                fma2(acc[2*j+0], s2, u.x);
                fma2(acc[2*j+1], s2, u.y);
            }
        }
    }

    const int base = tok * 32;
    #pragma unroll
    for (int i = 0; i < 8; i++) {
        float4 xv = *reinterpret_cast<const float4*>(out + base + 4 * i);
        float a0, a1, b0, b1;
        upk2(acc[2*i+0], a0, a1);
        upk2(acc[2*i+1], b0, b1);
        float4 r;
        r.x = xv.x + a0 + sb2[4*i+0];
        r.y = xv.y + a1 + sb2[4*i+1];
        r.z = xv.z + b0 + sb2[4*i+2];
        r.w = xv.w + b1 + sb2[4*i+3];
        *reinterpret_cast<float4*>(out + base + 4 * i) = r;
    }
}

// ---- launch -------------------------------------------------------------------
extern "C" void kernel_launch(void* const* d_in, const int* in_sizes, int n_in,
                              void* d_out, int out_size) {
    const float* x          = (const float*)d_in[0];
    const float* g1         = (const float*)d_in[1];
    const float* beta1      = (const float*)d_in[2];
    const float* Wq         = (const float*)d_in[3];
    const float* bq         = (const float*)d_in[4];
    const float* Wkv        = (const float*)d_in[5];
    const float* bkv        = (const float*)d_in[6];
    const float* bias_table = (const float*)d_in[7];
    const float* Wp         = (const float*)d_in[8];
    const float* bp         = (const float*)d_in[9];
    const float* g2         = (const float*)d_in[10];
    const float* beta2      = (const float*)d_in[11];
    const float* W1         = (const float*)d_in[12];
    const float* b1m        = (const float*)d_in[13];
    const float* dw_k       = (const float*)d_in[14];
    const float* dw_b       = (const float*)d_in[15];
    const float* W2         = (const float*)d_in[16];
    const float* b2m        = (const float*)d_in[17];
    const int*   rel_idx    = (const int*)d_in[18];
    float* out = (float*)d_out;

    kbias<<<16, 256>>>(bias_table, rel_idx);
    ka_attn<<<4096, 128>>>(x, g1, beta1, Wq, bq, Wkv, bkv, Wp, bp, out);
    kb1<<<2048, 256>>>(out, g2, beta2, W1, b1m);
    kconv<<<16384, 256>>>(dw_k, dw_b);
    kw2<<<2048, 256>>>(W2, b2m, out);
}